// round 4
// baseline (speedup 1.0000x reference)
#include <cuda_runtime.h>

// Problem dims
#define NN    128            // H == W == kernel_size
#define NH    65             // half-spectrum width (N/2+1)
#define NHP   68             // padded row stride for Yc
#define NB    32             // batch
#define NC    64             // in channels
#define NO    64             // out channels
#define NBC   (NB*NC)        // 2048
#define NBO   (NB*NO)        // 2048
#define NFREQ (NH*NN)        // 8320, f = wp*128 + h
#define LDF   129            // smem FFT row stride

// ---------------- scratch (device globals; allocation-free rule) ----------------
__device__ float2 g_X1[(size_t)NBC * NH * NN];     // [b*c][wp][h]
__device__ float2 g_Xf[(size_t)NFREQ * NB * NC];   // [f][b][c]
__device__ float2 g_Wf[(size_t)NFREQ * NC * NO];   // [f][c][o]
__device__ float2 g_Yf[(size_t)NFREQ * NB * NO];   // [f][b][o]
__device__ float2 g_Yc[(size_t)NBO * NN * NHP];    // [bo][h][wp]

// ---------------- packed f32x2 helpers (FFMA2) ----------------
__device__ __forceinline__ unsigned long long pk2(float x, float y) {
    unsigned long long r;
    asm("mov.b64 %0, {%1, %2};" : "=l"(r) : "f"(x), "f"(y));
    return r;
}
__device__ __forceinline__ void ffma2(unsigned long long& d, unsigned long long a, unsigned long long b) {
    asm("fma.rn.f32x2 %0, %1, %2, %0;" : "+l"(d) : "l"(a), "l"(b));
}
__device__ __forceinline__ float2 unpk2(unsigned long long v) {
    float2 f;
    asm("mov.b64 {%0, %1}, %2;" : "=f"(f.x), "=f"(f.y) : "l"(v));
    return f;
}

// ---------------- FFT helpers ----------------
__device__ __forceinline__ void init_tw(float2* tw) {
    int tid = threadIdx.x;
    if (tid < 64) {
        float s, c;
        sincospif(-(float)tid * (1.0f / 64.0f), &s, &c);
        tw[tid] = make_float2(c, s);
    }
}

__device__ __forceinline__ float2 f2add(float2 a, float2 b) { return make_float2(a.x + b.x, a.y + b.y); }
__device__ __forceinline__ float2 f2sub(float2 a, float2 b) { return make_float2(a.x - b.x, a.y - b.y); }

template <int SIGN>
__device__ __forceinline__ float2 cmul_tw(float2 w, float2 z) {
    float wy = (SIGN < 0) ? w.y : -w.y;
    return make_float2(z.x * w.x - z.y * wy, z.x * wy + z.y * w.x);
}

#define SWZI(p) ((p) ^ ((((unsigned)(p)) >> 4) & 7))

// Fused 3x radix-2 (= radix-8) Stockham group. 16 threads per FFT.
template <int SIGN, int S, bool SWZ_ST, bool SWZ_LD>
__device__ __forceinline__ void radix8_group(const float2* src, float2* dst, const float2* tw) {
    int tid = threadIdx.x;
    int fi = tid >> 4;
    int i  = tid & 15;
    const int tk = i & ~(S - 1);
    const float2* Sr = src + fi * LDF;
    float2* Dr = dst + fi * LDF;

    float2 a[8];
#pragma unroll
    for (int k = 0; k < 8; k++) {
        int p = i + 16 * k;
        if (SWZ_LD) p = SWZI(p);
        a[k] = Sr[p];
    }
    float2 v[4], u[4];
#pragma unroll
    for (int k = 0; k < 4; k++) {
        v[k] = f2add(a[k], a[k + 4]);
        u[k] = cmul_tw<SIGN>(tw[tk + 16 * k], f2sub(a[k], a[k + 4]));
    }
    float2 w0 = tw[2 * tk], w1 = tw[2 * tk + 32];
    float2 g[4], h[4];
    g[0] = f2add(v[0], v[2]);  g[2] = cmul_tw<SIGN>(w0, f2sub(v[0], v[2]));
    g[1] = f2add(u[0], u[2]);  g[3] = cmul_tw<SIGN>(w0, f2sub(u[0], u[2]));
    h[0] = f2add(v[1], v[3]);  h[2] = cmul_tw<SIGN>(w1, f2sub(v[1], v[3]));
    h[1] = f2add(u[1], u[3]);  h[3] = cmul_tw<SIGN>(w1, f2sub(u[1], u[3]));
    float2 w2 = tw[4 * tk];
    float2 e[8];
#pragma unroll
    for (int k = 0; k < 4; k++) {
        e[k]     = f2add(g[k], h[k]);
        e[k + 4] = cmul_tw<SIGN>(w2, f2sub(g[k], h[k]));
    }
    const int Q = i + 7 * tk;
#pragma unroll
    for (int k = 0; k < 8; k++) {
        int p = Q + k * S;
        if (SWZ_ST) p = SWZI(p);
        Dr[p] = e[k];
    }
}

// 16 FFTs of length 128 per 256-thread block. Input bufA, result bufB.
template <int SIGN>
__device__ __forceinline__ void fft128_block16(float2* bufA, float2* bufB, const float2* tw) {
    radix8_group<SIGN, 1, true,  false>(bufA, bufB, tw);
    __syncthreads();
    radix8_group<SIGN, 8, false, true >(bufB, bufA, tw);
    __syncthreads();
    int tid = threadIdx.x;
#pragma unroll
    for (int itb = 0; itb < 4; itb++) {
        int it  = tid + itb * 256;
        int f2  = it >> 6;
        int idx = it & 63;
        float2 x = bufA[f2 * LDF + idx];
        float2 y = bufA[f2 * LDF + idx + 64];
        bufB[f2 * LDF + idx]      = f2add(x, y);
        bufB[f2 * LDF + idx + 64] = f2sub(x, y);
    }
    __syncthreads();
}

// ---------------- K1: forward row FFT, transpose to [bc][wp][h]
__global__ void __launch_bounds__(256) k1_rowfft(const float* __restrict__ x) {
    __shared__ float2 bufA[16 * LDF], bufB[16 * LDF];
    __shared__ float2 tw[64];
    init_tw(tw);
    int tid = threadIdx.x;
    int blk = blockIdx.x;
    int bc = blk >> 3;
    int h0 = (blk & 7) << 4;
    const float* xp = x + (size_t)bc * NN * NN + (size_t)h0 * NN;
    for (int i = tid; i < 16 * NN; i += 256) {
        int r = i >> 7, w = i & 127;
        bufA[r * LDF + w] = make_float2(xp[i], 0.f);
    }
    __syncthreads();
    fft128_block16<-1>(bufA, bufB, tw);
    float2* out = g_X1 + (size_t)bc * NH * NN;
    for (int i = tid; i < NH * 16; i += 256) {
        int wp = i >> 4, r = i & 15;
        out[(size_t)wp * NN + h0 + r] = bufB[r * LDF + wp];
    }
}

// ---------------- K2: forward column FFT, scatter to freq-major [f][b][c]
__global__ void __launch_bounds__(256) k2_colfft() {
    __shared__ float2 bufA[16 * LDF], bufB[16 * LDF];
    __shared__ float2 tw[64];
    init_tw(tw);
    int tid = threadIdx.x;
    int blk = blockIdx.x;
    int b   = blk / (NH * 4);
    int rem = blk % (NH * 4);
    int wp  = rem >> 2;
    int c0  = (rem & 3) << 4;
    for (int i = tid; i < 16 * NN; i += 256) {
        int h = i & 127, cl = i >> 7;
        bufA[cl * LDF + h] =
            g_X1[((size_t)(b * NC + c0 + cl) * NH + wp) * NN + h];
    }
    __syncthreads();
    fft128_block16<-1>(bufA, bufB, tw);
    for (int i = tid; i < 16 * NN; i += 256) {
        int cl = i & 15, h = i >> 4;
        g_Xf[((size_t)(wp * NN + h)) * NBC + b * NC + c0 + cl] = bufB[cl * LDF + h];
    }
}

// ---------------- KW: mirror-pair Hermitianization, each weight element read ONCE.
// Block covers (c, hh in [0,64], wp-chunk). Produces output rows hh AND 128-hh.
// Weff(wp,h) = 0.5*(W(h,wp) + conj(W(h2,w2))),  h2=(128-h)&127, w2=(128-wp)&127.
__global__ void __launch_bounds__(256) kw_weff(const float* __restrict__ wr,
                                               const float* __restrict__ wi) {
    __shared__ float L1r[64][17], L1i[64][17];   // row hh, cols wp
    __shared__ float L2r[64][17], L2i[64][17];   // row hh, cols w2
    __shared__ float L3r[64][17], L3i[64][17];   // row h2, cols wp
    __shared__ float L4r[64][17], L4i[64][17];   // row h2, cols w2
    int tid = threadIdx.x;
    int blk = blockIdx.x;                 // c*(65*5) + hh*5 + wt
    int c   = blk / (NH * 5);
    int rem = blk % (NH * 5);
    int hh  = rem / 5;
    int wt  = rem % 5;
    int wp0 = wt << 4;
    int h2  = (NN - hh) & 127;

    for (int i = tid; i < 1024; i += 256) {
        int wl = i & 15, o = i >> 4;
        int cd = wp0 + wl;                       // direct col (<80, in-bounds)
        int cm = (NN - cd) & 127;                // mirror col
        size_t base = (size_t)(o * NC + c) * (NN * NN);
        const float* wrh  = wr + base + (size_t)hh * NN;
        const float* wih  = wi + base + (size_t)hh * NN;
        const float* wrh2 = wr + base + (size_t)h2 * NN;
        const float* wih2 = wi + base + (size_t)h2 * NN;
        L1r[o][wl] = wrh[cd];   L1i[o][wl] = wih[cd];
        L2r[o][wl] = wrh[cm];   L2i[o][wl] = wih[cm];
        L3r[o][wl] = wrh2[cd];  L3i[o][wl] = wih2[cd];
        L4r[o][wl] = wrh2[cm];  L4i[o][wl] = wih2[cm];
    }
    __syncthreads();

    for (int i = tid; i < 1024; i += 256) {
        int o = i & 63, wl = i >> 6;
        int wp = wp0 + wl;
        if (wp < NH) {
            // out row hh: 0.5*(L1 + conj(L4))
            g_Wf[((size_t)(wp * NN + hh)) * (NC * NO) + c * NO + o] =
                make_float2(0.5f * (L1r[o][wl] + L4r[o][wl]),
                            0.5f * (L1i[o][wl] - L4i[o][wl]));
            // out row h2: 0.5*(L3 + conj(L2))
            if (h2 != hh)
                g_Wf[((size_t)(wp * NN + h2)) * (NC * NO) + c * NO + o] =
                    make_float2(0.5f * (L3r[o][wl] + L2r[o][wl]),
                                0.5f * (L3i[o][wl] - L2i[o][wl]));
        }
    }
}

// ---------------- K3: per-frequency complex GEMM  Y[b][o] = sum_c X[b][c] * Weff[c][o]
// 128 threads, each computes 4 batches x 4 outputs (16 complex accumulators).
__global__ void __launch_bounds__(128) k3_contract() {
    __shared__ __align__(16) float Xr_s[NC][NB + 4];   // +4 pad keeps rows 16B-aligned
    __shared__ __align__(16) float Xi_s[NC][NB + 4];
    __shared__ __align__(16) float Wr[NC][NO];
    __shared__ __align__(16) float Wi[NC][NO];
    int tid = threadIdx.x;
    int f = blockIdx.x;
    const float2* __restrict__ Xg = g_Xf + (size_t)f * (NB * NC);
    const float2* __restrict__ Wg = g_Wf + (size_t)f * (NC * NO);
    for (int i = tid; i < NB * NC; i += 128) {
        float2 v = Xg[i];
        int b = i >> 6, c = i & 63;
        Xr_s[c][b] = v.x;
        Xi_s[c][b] = v.y;
    }
    for (int i = tid; i < NC * NO; i += 128) {
        float2 v = Wg[i];
        int c = i >> 6, o = i & 63;
        Wr[c][o] = v.x;
        Wi[c][o] = v.y;
    }
    __syncthreads();

    int b0 = (tid & 7) << 2;              // 4 batches per thread
    int o0 = (tid >> 3) << 2;             // 4 outputs per thread (2 o-pairs)
    unsigned long long ar[4][2], ai[4][2];
#pragma unroll
    for (int bb = 0; bb < 4; bb++)
#pragma unroll
        for (int op = 0; op < 2; op++) { ar[bb][op] = 0ull; ai[bb][op] = 0ull; }

#pragma unroll 2
    for (int c = 0; c < NC; c++) {
        float4 xr = *(const float4*)&Xr_s[c][b0];
        float4 xi = *(const float4*)&Xi_s[c][b0];
        float4 wrv = *(const float4*)&Wr[c][o0];
        float4 wiv = *(const float4*)&Wi[c][o0];
        unsigned long long wr01 = pk2(wrv.x, wrv.y);
        unsigned long long wr23 = pk2(wrv.z, wrv.w);
        unsigned long long wi01 = pk2(wiv.x, wiv.y);
        unsigned long long wi23 = pk2(wiv.z, wiv.w);
        const float* xrp = &xr.x;
        const float* xip = &xi.x;
#pragma unroll
        for (int bb = 0; bb < 4; bb++) {
            float xrb = xrp[bb];
            float xib = xip[bb];
            unsigned long long xr2 = pk2(xrb, xrb);
            unsigned long long xi2 = pk2(xib, xib);
            unsigned long long xn2 = pk2(-xib, -xib);
            ffma2(ar[bb][0], xr2, wr01);
            ffma2(ar[bb][0], xn2, wi01);
            ffma2(ai[bb][0], xr2, wi01);
            ffma2(ai[bb][0], xi2, wr01);
            ffma2(ar[bb][1], xr2, wr23);
            ffma2(ar[bb][1], xn2, wi23);
            ffma2(ai[bb][1], xr2, wi23);
            ffma2(ai[bb][1], xi2, wr23);
        }
    }
    float2* Yg = g_Yf + (size_t)f * (NB * NO);
#pragma unroll
    for (int bb = 0; bb < 4; bb++)
#pragma unroll
        for (int op = 0; op < 2; op++) {
            float2 arv = unpk2(ar[bb][op]);
            float2 aiv = unpk2(ai[bb][op]);
            float4 o2 = make_float4(arv.x, aiv.x, arv.y, aiv.y);
            *(float4*)&Yg[(b0 + bb) * NO + o0 + 2 * op] = o2;
        }
}

// ---------------- K4: inverse column FFT (along h), to [bo][h][wp] (padded)
__global__ void __launch_bounds__(256) k4_colifft() {
    __shared__ float2 bufA[16 * LDF], bufB[16 * LDF];
    __shared__ float2 tw[64];
    init_tw(tw);
    int tid = threadIdx.x;
    int blk = blockIdx.x;
    int bt = blk / 17;
    int wt = blk % 17;
    int bo0 = bt << 2;
    int wp0 = wt << 2;
    for (int i = tid; i < 16 * NN; i += 256) {
        int bl = i & 3, wl = (i >> 2) & 3, h = i >> 4;
        int wp = wp0 + wl;
        int fi = (wl << 2) + bl;
        float2 v = make_float2(0.f, 0.f);
        if (wp < NH)
            v = g_Yf[((size_t)(wp * NN + h)) * NBO + bo0 + bl];
        bufA[fi * LDF + h] = v;
    }
    __syncthreads();
    fft128_block16<1>(bufA, bufB, tw);
    for (int i = tid; i < 16 * NN; i += 256) {
        int wl = i & 3, bl = (i >> 2) & 3, h = i >> 4;
        int wp = wp0 + wl;
        int fi = (wl << 2) + bl;
        if (wp < NH)
            g_Yc[((size_t)(bo0 + bl) * NN + h) * NHP + wp] = bufB[fi * LDF + h];
    }
}

// ---------------- K5: inverse row FFT (Hermitian mirror), scale + bias + relu
__global__ void __launch_bounds__(256) k5_rowifft(const float* __restrict__ bias,
                                                  float* __restrict__ out) {
    __shared__ float2 bufA[16 * LDF], bufB[16 * LDF];
    __shared__ float2 tw[64];
    init_tw(tw);
    int tid = threadIdx.x;
    int blk = blockIdx.x;
    int bo = blk >> 3;
    int h0 = (blk & 7) << 4;
    int o  = bo & 63;
    const float2* Yrow = g_Yc + (size_t)bo * NN * NHP;
    for (int i = tid; i < 16 * NN; i += 256) {
        int r = i >> 7, w = i & 127;
        int wp = (w <= 64) ? w : (NN - w);
        float2 v = Yrow[(size_t)(h0 + r) * NHP + wp];
        if (w > 64) v.y = -v.y;           // conj mirror
        bufA[r * LDF + w] = v;
    }
    __syncthreads();
    fft128_block16<1>(bufA, bufB, tw);
    float bv = bias[o];
    const float scale = 1.0f / 16384.0f;
    float* op = out + (size_t)bo * NN * NN + (size_t)h0 * NN;
    for (int i = tid; i < 16 * NN; i += 256) {
        int r = i >> 7, w = i & 127;
        float val = bufB[r * LDF + w].x * scale + bv;
        op[(size_t)r * NN + w] = fmaxf(val, 0.f);
    }
}

// ---------------- launch ----------------
extern "C" void kernel_launch(void* const* d_in, const int* in_sizes, int n_in,
                              void* d_out, int out_size) {
    const float* x    = (const float*)d_in[0];
    const float* wr   = (const float*)d_in[1];
    const float* wi   = (const float*)d_in[2];
    const float* bias = (const float*)d_in[3];
    float* out = (float*)d_out;

    k1_rowfft <<<NBC * 8, 256>>>(x);             // 16384 blocks
    kw_weff   <<<NC * NH * 5, 256>>>(wr, wi);    // 20800 blocks
    k2_colfft <<<NB * NH * 4, 256>>>();          // 8320 blocks
    k3_contract<<<NFREQ, 128>>>();               // 8320 blocks
    k4_colifft<<<(NBO / 4) * 17, 256>>>();       // 8704 blocks
    k5_rowifft<<<NBO * 8, 256>>>(bias, out);     // 16384 blocks
}

// round 5
// speedup vs baseline: 1.2622x; 1.2622x over previous
#include <cuda_runtime.h>

// Problem dims
#define NN    128            // H == W == kernel_size
#define NH    65             // half-spectrum width (N/2+1)
#define NHP   68             // padded row stride for Yc
#define NB    32             // batch
#define NC    64             // in channels
#define NO    64             // out channels
#define NBC   (NB*NC)        // 2048
#define NBO   (NB*NO)        // 2048
#define NFREQ (NH*NN)        // 8320, f = wp*128 + h
#define LDF   129            // smem FFT row stride

// ---------------- scratch (device globals; allocation-free rule) ----------------
__device__ float2 g_X1[(size_t)NBC * NH * NN];     // [b*c][wp][h]
__device__ float2 g_Xf[(size_t)NFREQ * NB * NC];   // [f][b][c]
__device__ float2 g_Wf[(size_t)NFREQ * NC * NO];   // [f][c][o]
__device__ float2 g_Yf[(size_t)NFREQ * NB * NO];   // [f][b][o]
__device__ float2 g_Yc[(size_t)NBO * NN * NHP];    // [bo][h][wp]

// ---------------- packed f32x2 helpers (FFMA2) ----------------
__device__ __forceinline__ unsigned long long pk2(float x, float y) {
    unsigned long long r;
    asm("mov.b64 %0, {%1, %2};" : "=l"(r) : "f"(x), "f"(y));
    return r;
}
__device__ __forceinline__ void ffma2(unsigned long long& d, unsigned long long a, unsigned long long b) {
    asm("fma.rn.f32x2 %0, %1, %2, %0;" : "+l"(d) : "l"(a), "l"(b));
}
__device__ __forceinline__ float2 unpk2(unsigned long long v) {
    float2 f;
    asm("mov.b64 {%0, %1}, %2;" : "=f"(f.x), "=f"(f.y) : "l"(v));
    return f;
}

// ---------------- FFT helpers ----------------
__device__ __forceinline__ void init_tw(float2* tw) {
    int tid = threadIdx.x;
    if (tid < 64) {
        float s, c;
        sincospif(-(float)tid * (1.0f / 64.0f), &s, &c);
        tw[tid] = make_float2(c, s);
    }
}

__device__ __forceinline__ float2 f2add(float2 a, float2 b) { return make_float2(a.x + b.x, a.y + b.y); }
__device__ __forceinline__ float2 f2sub(float2 a, float2 b) { return make_float2(a.x - b.x, a.y - b.y); }

template <int SIGN>
__device__ __forceinline__ float2 cmul_tw(float2 w, float2 z) {
    float wy = (SIGN < 0) ? w.y : -w.y;
    return make_float2(z.x * w.x - z.y * wy, z.x * wy + z.y * w.x);
}

#define SWZI(p) ((p) ^ ((((unsigned)(p)) >> 4) & 7))

// Fused 3x radix-2 (= radix-8) Stockham group. 16 threads per FFT.
template <int SIGN, int S, bool SWZ_ST, bool SWZ_LD>
__device__ __forceinline__ void radix8_group(const float2* src, float2* dst, const float2* tw) {
    int tid = threadIdx.x;
    int fi = tid >> 4;
    int i  = tid & 15;
    const int tk = i & ~(S - 1);
    const float2* Sr = src + fi * LDF;
    float2* Dr = dst + fi * LDF;

    float2 a[8];
#pragma unroll
    for (int k = 0; k < 8; k++) {
        int p = i + 16 * k;
        if (SWZ_LD) p = SWZI(p);
        a[k] = Sr[p];
    }
    float2 v[4], u[4];
#pragma unroll
    for (int k = 0; k < 4; k++) {
        v[k] = f2add(a[k], a[k + 4]);
        u[k] = cmul_tw<SIGN>(tw[tk + 16 * k], f2sub(a[k], a[k + 4]));
    }
    float2 w0 = tw[2 * tk], w1 = tw[2 * tk + 32];
    float2 g[4], h[4];
    g[0] = f2add(v[0], v[2]);  g[2] = cmul_tw<SIGN>(w0, f2sub(v[0], v[2]));
    g[1] = f2add(u[0], u[2]);  g[3] = cmul_tw<SIGN>(w0, f2sub(u[0], u[2]));
    h[0] = f2add(v[1], v[3]);  h[2] = cmul_tw<SIGN>(w1, f2sub(v[1], v[3]));
    h[1] = f2add(u[1], u[3]);  h[3] = cmul_tw<SIGN>(w1, f2sub(u[1], u[3]));
    float2 w2 = tw[4 * tk];
    float2 e[8];
#pragma unroll
    for (int k = 0; k < 4; k++) {
        e[k]     = f2add(g[k], h[k]);
        e[k + 4] = cmul_tw<SIGN>(w2, f2sub(g[k], h[k]));
    }
    const int Q = i + 7 * tk;
#pragma unroll
    for (int k = 0; k < 8; k++) {
        int p = Q + k * S;
        if (SWZ_ST) p = SWZI(p);
        Dr[p] = e[k];
    }
}

// 16 FFTs of length 128 per 256-thread block. Input bufA, result bufB.
template <int SIGN>
__device__ __forceinline__ void fft128_block16(float2* bufA, float2* bufB, const float2* tw) {
    radix8_group<SIGN, 1, true,  false>(bufA, bufB, tw);
    __syncthreads();
    radix8_group<SIGN, 8, false, true >(bufB, bufA, tw);
    __syncthreads();
    int tid = threadIdx.x;
#pragma unroll
    for (int itb = 0; itb < 4; itb++) {
        int it  = tid + itb * 256;
        int f2  = it >> 6;
        int idx = it & 63;
        float2 x = bufA[f2 * LDF + idx];
        float2 y = bufA[f2 * LDF + idx + 64];
        bufB[f2 * LDF + idx]      = f2add(x, y);
        bufB[f2 * LDF + idx + 64] = f2sub(x, y);
    }
    __syncthreads();
}

// ---------------- K1: forward row FFT with real-pair packing.
// 32 real rows per block -> 16 complex FFTs (z = row_{2p} + i*row_{2p+1}).
// Unpack: X0 = (Z[k]+conj(Z[-k]))/2, X1 = (Z[k]-conj(Z[-k]))/(2i).
__global__ void __launch_bounds__(256) k1_rowfft(const float* __restrict__ x) {
    __shared__ float2 bufA[16 * LDF], bufB[16 * LDF];
    __shared__ float2 tw[64];
    init_tw(tw);
    int tid = threadIdx.x;
    int blk = blockIdx.x;
    int bc = blk >> 2;
    int h0 = (blk & 3) << 5;              // 32 rows
    const float* xp = x + (size_t)bc * NN * NN + (size_t)h0 * NN;
    for (int i = tid; i < 16 * NN; i += 256) {
        int p = i >> 7, w = i & 127;
        bufA[p * LDF + w] = make_float2(xp[(2 * p) * NN + w], xp[(2 * p + 1) * NN + w]);
    }
    __syncthreads();
    fft128_block16<-1>(bufA, bufB, tw);
    float2* out = g_X1 + (size_t)bc * NH * NN;
    for (int i = tid; i < NH * 16; i += 256) {
        int p = i & 15, wp = i >> 4;
        float2 A = bufB[p * LDF + wp];
        float2 B = bufB[p * LDF + ((NN - wp) & 127)];
        float2 X0 = make_float2(0.5f * (A.x + B.x), 0.5f * (A.y - B.y));
        float2 X1 = make_float2(0.5f * (A.y + B.y), 0.5f * (B.x - A.x));
        float4 o2 = make_float4(X0.x, X0.y, X1.x, X1.y);
        *(float4*)&out[(size_t)wp * NN + h0 + 2 * p] = o2;
    }
}

// ---------------- K2: forward column FFT, scatter to freq-major [f][b][c]
__global__ void __launch_bounds__(256) k2_colfft() {
    __shared__ float2 bufA[16 * LDF], bufB[16 * LDF];
    __shared__ float2 tw[64];
    init_tw(tw);
    int tid = threadIdx.x;
    int blk = blockIdx.x;
    int b   = blk / (NH * 4);
    int rem = blk % (NH * 4);
    int wp  = rem >> 2;
    int c0  = (rem & 3) << 4;
    for (int i = tid; i < 16 * NN; i += 256) {
        int h = i & 127, cl = i >> 7;
        bufA[cl * LDF + h] =
            g_X1[((size_t)(b * NC + c0 + cl) * NH + wp) * NN + h];
    }
    __syncthreads();
    fft128_block16<-1>(bufA, bufB, tw);
    for (int i = tid; i < 16 * NN; i += 256) {
        int cl = i & 15, h = i >> 4;
        g_Xf[((size_t)(wp * NN + h)) * NBC + b * NC + c0 + cl] = bufB[cl * LDF + h];
    }
}

// ---------------- KW: Weff[f][c][o] = 0.5*(W[k] + conj(W[-k]))  (R2 version)
__global__ void __launch_bounds__(256) kw_weff(const float* __restrict__ wr,
                                               const float* __restrict__ wi) {
    __shared__ float2 S[64][17];
    int tid = threadIdx.x;
    int blk = blockIdx.x;                 // c*(128*5) + h*5 + wt
    int c   = blk / (NN * 5);
    int rem = blk % (NN * 5);
    int h   = rem / 5;
    int wt  = rem % 5;
    int wp0 = wt << 4;
    int h2  = (NN - h) & 127;
    for (int i = tid; i < 1024; i += 256) {
        int wl = i & 15, o = i >> 4;
        int wp = wp0 + wl;
        int w2 = (NN - wp) & 127;
        size_t base = (size_t)(o * NC + c) * (NN * NN);
        float a1 = wr[base + (size_t)h  * NN + wp];
        float b1 = wi[base + (size_t)h  * NN + wp];
        float a2 = wr[base + (size_t)h2 * NN + w2];
        float b2 = wi[base + (size_t)h2 * NN + w2];
        S[o][wl] = make_float2(0.5f * (a1 + a2), 0.5f * (b1 - b2));
    }
    __syncthreads();
    for (int i = tid; i < 1024; i += 256) {
        int o = i & 63, wl = i >> 6;
        int wp = wp0 + wl;
        if (wp < NH)
            g_Wf[((size_t)(wp * NN + h)) * (NC * NO) + c * NO + o] = S[o][wl];
    }
}

// ---------------- K3: per-frequency complex GEMM  Y[b][o] = sum_c X[b][c] * Weff[c][o]
// 128 threads; each thread: 2 outputs x 8 batches. Batch values are packed in
// pairs (free: adjacent floats); only the 2x3 weight broadcasts need dup MOVs.
__global__ void __launch_bounds__(128) k3_contract() {
    __shared__ __align__(16) float Xr_s[NC][NB + 4];   // rows 16B-aligned
    __shared__ __align__(16) float Xi_s[NC][NB + 4];
    __shared__ __align__(16) float Wr[NC][NO];
    __shared__ __align__(16) float Wi[NC][NO];
    int tid = threadIdx.x;
    int f = blockIdx.x;
    const float2* __restrict__ Xg = g_Xf + (size_t)f * (NB * NC);
    const float2* __restrict__ Wg = g_Wf + (size_t)f * (NC * NO);
    for (int i = tid; i < NB * NC; i += 128) {
        float2 v = Xg[i];
        int b = i >> 6, c = i & 63;
        Xr_s[c][b] = v.x;
        Xi_s[c][b] = v.y;
    }
    for (int i = tid; i < NC * NO; i += 128) {
        float2 v = Wg[i];
        int c = i >> 6, o = i & 63;
        Wr[c][o] = v.x;
        Wi[c][o] = v.y;
    }
    __syncthreads();

    int b0 = (tid & 3) << 3;              // 8 batches per thread
    int o0 = (tid >> 2) << 1;             // 2 outputs per thread
    unsigned long long ar[2][4], ai[2][4];
#pragma unroll
    for (int o = 0; o < 2; o++)
#pragma unroll
        for (int k = 0; k < 4; k++) { ar[o][k] = 0ull; ai[o][k] = 0ull; }

#pragma unroll 2
    for (int c = 0; c < NC; c++) {
        float4 xr0 = *(const float4*)&Xr_s[c][b0];
        float4 xr1 = *(const float4*)&Xr_s[c][b0 + 4];
        float4 xi0 = *(const float4*)&Xi_s[c][b0];
        float4 xi1 = *(const float4*)&Xi_s[c][b0 + 4];
        float2 wrv = *(const float2*)&Wr[c][o0];
        float2 wiv = *(const float2*)&Wi[c][o0];
        unsigned long long xrp[4], xip[4];
        xrp[0] = pk2(xr0.x, xr0.y); xrp[1] = pk2(xr0.z, xr0.w);
        xrp[2] = pk2(xr1.x, xr1.y); xrp[3] = pk2(xr1.z, xr1.w);
        xip[0] = pk2(xi0.x, xi0.y); xip[1] = pk2(xi0.z, xi0.w);
        xip[2] = pk2(xi1.x, xi1.y); xip[3] = pk2(xi1.z, xi1.w);
#pragma unroll
        for (int o = 0; o < 2; o++) {
            float wrs = o ? wrv.y : wrv.x;
            float wis = o ? wiv.y : wiv.x;
            unsigned long long wrd = pk2(wrs, wrs);
            unsigned long long wid = pk2(wis, wis);
            unsigned long long wnd = pk2(-wis, -wis);
#pragma unroll
            for (int k = 0; k < 4; k++) {
                ffma2(ar[o][k], xrp[k], wrd);   // ar += xr*wr
                ffma2(ar[o][k], xip[k], wnd);   // ar -= xi*wi
                ffma2(ai[o][k], xrp[k], wid);   // ai += xr*wi
                ffma2(ai[o][k], xip[k], wrd);   // ai += xi*wr
            }
        }
    }
    float2* Yg = g_Yf + (size_t)f * (NB * NO);
#pragma unroll
    for (int k = 0; k < 4; k++) {
        float2 a0r = unpk2(ar[0][k]);
        float2 a0i = unpk2(ai[0][k]);
        float2 a1r = unpk2(ar[1][k]);
        float2 a1i = unpk2(ai[1][k]);
        *(float4*)&Yg[(b0 + 2 * k) * NO + o0]     = make_float4(a0r.x, a0i.x, a1r.x, a1i.x);
        *(float4*)&Yg[(b0 + 2 * k + 1) * NO + o0] = make_float4(a0r.y, a0i.y, a1r.y, a1i.y);
    }
}

// ---------------- K4: inverse column FFT (along h), to [bo][h][wp] (padded)
__global__ void __launch_bounds__(256) k4_colifft() {
    __shared__ float2 bufA[16 * LDF], bufB[16 * LDF];
    __shared__ float2 tw[64];
    init_tw(tw);
    int tid = threadIdx.x;
    int blk = blockIdx.x;
    int bt = blk / 17;
    int wt = blk % 17;
    int bo0 = bt << 2;
    int wp0 = wt << 2;
    for (int i = tid; i < 16 * NN; i += 256) {
        int bl = i & 3, wl = (i >> 2) & 3, h = i >> 4;
        int wp = wp0 + wl;
        int fi = (wl << 2) + bl;
        float2 v = make_float2(0.f, 0.f);
        if (wp < NH)
            v = g_Yf[((size_t)(wp * NN + h)) * NBO + bo0 + bl];
        bufA[fi * LDF + h] = v;
    }
    __syncthreads();
    fft128_block16<1>(bufA, bufB, tw);
    for (int i = tid; i < 16 * NN; i += 256) {
        int wl = i & 3, bl = (i >> 2) & 3, h = i >> 4;
        int wp = wp0 + wl;
        int fi = (wl << 2) + bl;
        if (wp < NH)
            g_Yc[((size_t)(bo0 + bl) * NN + h) * NHP + wp] = bufB[fi * LDF + h];
    }
}

// ---------------- K5: inverse row FFT with real-pair packing.
// Rows are Hermitian (real output), so pack two rows: z = Y0 + i*Y1,
// ifft once; Re -> row 2p, Im -> row 2p+1. Then scale + bias + relu.
__global__ void __launch_bounds__(256) k5_rowifft(const float* __restrict__ bias,
                                                  float* __restrict__ out) {
    __shared__ float2 bufA[16 * LDF], bufB[16 * LDF];
    __shared__ float2 tw[64];
    init_tw(tw);
    int tid = threadIdx.x;
    int blk = blockIdx.x;
    int bo = blk >> 2;
    int h0 = (blk & 3) << 5;              // 32 rows = 16 pairs
    int o  = bo & 63;
    const float2* Yrow = g_Yc + (size_t)bo * NN * NHP;
    for (int i = tid; i < 16 * NN; i += 256) {
        int p = i >> 7, w = i & 127;
        int wp = (w <= 64) ? w : (NN - w);
        float2 A0 = Yrow[(size_t)(h0 + 2 * p)     * NHP + wp];
        float2 A1 = Yrow[(size_t)(h0 + 2 * p + 1) * NHP + wp];
        if (w > 64) { A0.y = -A0.y; A1.y = -A1.y; }
        // z = A0 + i*A1
        bufA[p * LDF + w] = make_float2(A0.x - A1.y, A0.y + A1.x);
    }
    __syncthreads();
    fft128_block16<1>(bufA, bufB, tw);
    float bv = bias[o];
    const float scale = 1.0f / 16384.0f;
    float* op = out + (size_t)bo * NN * NN;
    for (int i = tid; i < 16 * NN; i += 256) {
        int p = i >> 7, w = i & 127;
        float2 v = bufB[p * LDF + w];
        float v0 = v.x * scale + bv;
        float v1 = v.y * scale + bv;
        op[(size_t)(h0 + 2 * p)     * NN + w] = fmaxf(v0, 0.f);
        op[(size_t)(h0 + 2 * p + 1) * NN + w] = fmaxf(v1, 0.f);
    }
}

// ---------------- launch ----------------
extern "C" void kernel_launch(void* const* d_in, const int* in_sizes, int n_in,
                              void* d_out, int out_size) {
    const float* x    = (const float*)d_in[0];
    const float* wr   = (const float*)d_in[1];
    const float* wi   = (const float*)d_in[2];
    const float* bias = (const float*)d_in[3];
    float* out = (float*)d_out;

    k1_rowfft <<<NBC * 4, 256>>>(x);             // 8192 blocks
    kw_weff   <<<NC * NN * 5, 256>>>(wr, wi);    // 40960 blocks
    k2_colfft <<<NB * NH * 4, 256>>>();          // 8320 blocks
    k3_contract<<<NFREQ, 128>>>();               // 8320 blocks
    k4_colifft<<<(NBO / 4) * 17, 256>>>();       // 8704 blocks
    k5_rowifft<<<NBO * 4, 256>>>(bias, out);     // 8192 blocks
}

// round 6
// speedup vs baseline: 1.2787x; 1.0131x over previous
#include <cuda_runtime.h>
#include <cuda_fp16.h>

// Problem dims
#define NN    128            // H == W == kernel_size
#define NH    65             // half-spectrum width (N/2+1)
#define NHP   68             // padded row stride for Yc
#define NB    32             // batch
#define NC    64             // in channels
#define NO    64             // out channels
#define NBC   (NB*NC)        // 2048
#define NBO   (NB*NO)        // 2048
#define NFREQ (NH*NN)        // 8320, f = wp*128 + h
#define LDF   129            // smem FFT row stride
#define KWT   13             // kw tile width (5*13 = 65 = NH exactly)

// ---------------- scratch (device globals; allocation-free rule) ----------------
__device__ float2  g_X1[(size_t)NBC * NH * NN];     // [b*c][wp][h]
__device__ float2  g_Xf[(size_t)NFREQ * NB * NC];   // [f][b][c]
__device__ __half2 g_Wf[(size_t)NFREQ * NC * NO];   // [f][c][o]  fp16 (r,i)
__device__ float2  g_Yf[(size_t)NFREQ * NB * NO];   // [f][b][o]
__device__ float2  g_Yc[(size_t)NBO * NN * NHP];    // [bo][h][wp]

// ---------------- packed f32x2 helpers (FFMA2) ----------------
__device__ __forceinline__ unsigned long long pk2(float x, float y) {
    unsigned long long r;
    asm("mov.b64 %0, {%1, %2};" : "=l"(r) : "f"(x), "f"(y));
    return r;
}
__device__ __forceinline__ void ffma2(unsigned long long& d, unsigned long long a, unsigned long long b) {
    asm("fma.rn.f32x2 %0, %1, %2, %0;" : "+l"(d) : "l"(a), "l"(b));
}
__device__ __forceinline__ float2 unpk2(unsigned long long v) {
    float2 f;
    asm("mov.b64 {%0, %1}, %2;" : "=f"(f.x), "=f"(f.y) : "l"(v));
    return f;
}

// ---------------- FFT helpers ----------------
__device__ __forceinline__ void init_tw(float2* tw) {
    int tid = threadIdx.x;
    if (tid < 64) {
        float s, c;
        sincospif(-(float)tid * (1.0f / 64.0f), &s, &c);
        tw[tid] = make_float2(c, s);
    }
}

__device__ __forceinline__ float2 f2add(float2 a, float2 b) { return make_float2(a.x + b.x, a.y + b.y); }
__device__ __forceinline__ float2 f2sub(float2 a, float2 b) { return make_float2(a.x - b.x, a.y - b.y); }

template <int SIGN>
__device__ __forceinline__ float2 cmul_tw(float2 w, float2 z) {
    float wy = (SIGN < 0) ? w.y : -w.y;
    return make_float2(z.x * w.x - z.y * wy, z.x * wy + z.y * w.x);
}

#define SWZI(p) ((p) ^ ((((unsigned)(p)) >> 4) & 7))

// Fused 3x radix-2 (= radix-8) Stockham group. 16 threads per FFT.
template <int SIGN, int S, bool SWZ_ST, bool SWZ_LD>
__device__ __forceinline__ void radix8_group(const float2* src, float2* dst, const float2* tw) {
    int tid = threadIdx.x;
    int fi = tid >> 4;
    int i  = tid & 15;
    const int tk = i & ~(S - 1);
    const float2* Sr = src + fi * LDF;
    float2* Dr = dst + fi * LDF;

    float2 a[8];
#pragma unroll
    for (int k = 0; k < 8; k++) {
        int p = i + 16 * k;
        if (SWZ_LD) p = SWZI(p);
        a[k] = Sr[p];
    }
    float2 v[4], u[4];
#pragma unroll
    for (int k = 0; k < 4; k++) {
        v[k] = f2add(a[k], a[k + 4]);
        u[k] = cmul_tw<SIGN>(tw[tk + 16 * k], f2sub(a[k], a[k + 4]));
    }
    float2 w0 = tw[2 * tk], w1 = tw[2 * tk + 32];
    float2 g[4], h[4];
    g[0] = f2add(v[0], v[2]);  g[2] = cmul_tw<SIGN>(w0, f2sub(v[0], v[2]));
    g[1] = f2add(u[0], u[2]);  g[3] = cmul_tw<SIGN>(w0, f2sub(u[0], u[2]));
    h[0] = f2add(v[1], v[3]);  h[2] = cmul_tw<SIGN>(w1, f2sub(v[1], v[3]));
    h[1] = f2add(u[1], u[3]);  h[3] = cmul_tw<SIGN>(w1, f2sub(u[1], u[3]));
    float2 w2 = tw[4 * tk];
    float2 e[8];
#pragma unroll
    for (int k = 0; k < 4; k++) {
        e[k]     = f2add(g[k], h[k]);
        e[k + 4] = cmul_tw<SIGN>(w2, f2sub(g[k], h[k]));
    }
    const int Q = i + 7 * tk;
#pragma unroll
    for (int k = 0; k < 8; k++) {
        int p = Q + k * S;
        if (SWZ_ST) p = SWZI(p);
        Dr[p] = e[k];
    }
}

// 16 FFTs of length 128 per 256-thread block. Input bufA, result bufB.
template <int SIGN>
__device__ __forceinline__ void fft128_block16(float2* bufA, float2* bufB, const float2* tw) {
    radix8_group<SIGN, 1, true,  false>(bufA, bufB, tw);
    __syncthreads();
    radix8_group<SIGN, 8, false, true >(bufB, bufA, tw);
    __syncthreads();
    int tid = threadIdx.x;
#pragma unroll
    for (int itb = 0; itb < 4; itb++) {
        int it  = tid + itb * 256;
        int f2  = it >> 6;
        int idx = it & 63;
        float2 x = bufA[f2 * LDF + idx];
        float2 y = bufA[f2 * LDF + idx + 64];
        bufB[f2 * LDF + idx]      = f2add(x, y);
        bufB[f2 * LDF + idx + 64] = f2sub(x, y);
    }
    __syncthreads();
}

// ---------------- K1: forward row FFT with real-pair packing.
__global__ void __launch_bounds__(256) k1_rowfft(const float* __restrict__ x) {
    __shared__ float2 bufA[16 * LDF], bufB[16 * LDF];
    __shared__ float2 tw[64];
    init_tw(tw);
    int tid = threadIdx.x;
    int blk = blockIdx.x;
    int bc = blk >> 2;
    int h0 = (blk & 3) << 5;              // 32 rows
    const float* xp = x + (size_t)bc * NN * NN + (size_t)h0 * NN;
    for (int i = tid; i < 16 * NN; i += 256) {
        int p = i >> 7, w = i & 127;
        bufA[p * LDF + w] = make_float2(xp[(2 * p) * NN + w], xp[(2 * p + 1) * NN + w]);
    }
    __syncthreads();
    fft128_block16<-1>(bufA, bufB, tw);
    float2* out = g_X1 + (size_t)bc * NH * NN;
    for (int i = tid; i < NH * 16; i += 256) {
        int p = i & 15, wp = i >> 4;
        float2 A = bufB[p * LDF + wp];
        float2 B = bufB[p * LDF + ((NN - wp) & 127)];
        float2 X0 = make_float2(0.5f * (A.x + B.x), 0.5f * (A.y - B.y));
        float2 X1 = make_float2(0.5f * (A.y + B.y), 0.5f * (B.x - A.x));
        float4 o2 = make_float4(X0.x, X0.y, X1.x, X1.y);
        *(float4*)&out[(size_t)wp * NN + h0 + 2 * p] = o2;
    }
}

// ---------------- K2: forward column FFT, scatter to freq-major [f][b][c]
__global__ void __launch_bounds__(256) k2_colfft() {
    __shared__ float2 bufA[16 * LDF], bufB[16 * LDF];
    __shared__ float2 tw[64];
    init_tw(tw);
    int tid = threadIdx.x;
    int blk = blockIdx.x;
    int b   = blk / (NH * 4);
    int rem = blk % (NH * 4);
    int wp  = rem >> 2;
    int c0  = (rem & 3) << 4;
    for (int i = tid; i < 16 * NN; i += 256) {
        int h = i & 127, cl = i >> 7;
        bufA[cl * LDF + h] =
            g_X1[((size_t)(b * NC + c0 + cl) * NH + wp) * NN + h];
    }
    __syncthreads();
    fft128_block16<-1>(bufA, bufB, tw);
    for (int i = tid; i < 16 * NN; i += 256) {
        int cl = i & 15, h = i >> 4;
        g_Xf[((size_t)(wp * NN + h)) * NBC + b * NC + c0 + cl] = bufB[cl * LDF + h];
    }
}

// ---------------- KW: Weff[f][c][o] = 0.5*(W[k] + conj(W[-k])), fp16 output.
// Tile width 13 (5*13 = 65 = NH exactly): no dead columns read.
__global__ void __launch_bounds__(256) kw_weff(const float* __restrict__ wr,
                                               const float* __restrict__ wi) {
    __shared__ __half2 S[64][KWT + 3];
    int tid = threadIdx.x;
    int blk = blockIdx.x;                 // c*(128*5) + h*5 + wt
    int c   = blk / (NN * 5);
    int rem = blk % (NN * 5);
    int h   = rem / 5;
    int wt  = rem % 5;
    int wp0 = wt * KWT;
    int h2  = (NN - h) & 127;
    for (int i = tid; i < 64 * 16; i += 256) {
        int wl = i & 15, o = i >> 4;
        if (wl < KWT) {
            int wp = wp0 + wl;            // < 65
            int w2 = (NN - wp) & 127;
            size_t base = (size_t)(o * NC + c) * (NN * NN);
            float a1 = wr[base + (size_t)h  * NN + wp];
            float b1 = wi[base + (size_t)h  * NN + wp];
            float a2 = wr[base + (size_t)h2 * NN + w2];
            float b2 = wi[base + (size_t)h2 * NN + w2];
            S[o][wl] = __floats2half2_rn(0.5f * (a1 + a2), 0.5f * (b1 - b2));
        }
    }
    __syncthreads();
    for (int i = tid; i < 64 * 16; i += 256) {
        int o = i & 63, wl = i >> 6;
        if (wl < KWT) {
            int wp = wp0 + wl;
            g_Wf[((size_t)(wp * NN + h)) * (NC * NO) + c * NO + o] = S[o][wl];
        }
    }
}

// ---------------- K3: per-frequency complex GEMM  Y[b][o] = sum_c X[b][c] * Weff[c][o]
// 128 threads; each thread: 2 outputs x 8 batches. x operands load as
// ulonglong2 (LDS.128 -> two packed f32x2 regs, zero repack MOVs).
__global__ void __launch_bounds__(128) k3_contract() {
    __shared__ __align__(16) float Xr_s[NC][NB + 4];   // rows 16B-aligned
    __shared__ __align__(16) float Xi_s[NC][NB + 4];
    __shared__ __align__(16) float Wr[NC][NO];
    __shared__ __align__(16) float Wi[NC][NO];
    int tid = threadIdx.x;
    int f = blockIdx.x;
    const float2* __restrict__ Xg = g_Xf + (size_t)f * (NB * NC);
    const uint4* __restrict__ Wg4 = (const uint4*)(g_Wf + (size_t)f * (NC * NO));
    for (int i = tid; i < NB * NC; i += 128) {
        float2 v = Xg[i];
        int b = i >> 6, c = i & 63;
        Xr_s[c][b] = v.x;
        Xi_s[c][b] = v.y;
    }
    for (int i = tid; i < (NC * NO) / 4; i += 128) {   // uint4 = 4 half2 = 4 o's
        uint4 v = Wg4[i];
        int base = i * 4;
        int c = base >> 6, o = base & 63;
        float2 f0 = __half22float2(*(__half2*)&v.x);
        float2 f1 = __half22float2(*(__half2*)&v.y);
        float2 f2v = __half22float2(*(__half2*)&v.z);
        float2 f3 = __half22float2(*(__half2*)&v.w);
        Wr[c][o]     = f0.x;  Wi[c][o]     = f0.y;
        Wr[c][o + 1] = f1.x;  Wi[c][o + 1] = f1.y;
        Wr[c][o + 2] = f2v.x; Wi[c][o + 2] = f2v.y;
        Wr[c][o + 3] = f3.x;  Wi[c][o + 3] = f3.y;
    }
    __syncthreads();

    int b0 = (tid & 3) << 3;              // 8 batches per thread
    int o0 = (tid >> 2) << 1;             // 2 outputs per thread
    unsigned long long ar[2][4], ai[2][4];
#pragma unroll
    for (int o = 0; o < 2; o++)
#pragma unroll
        for (int k = 0; k < 4; k++) { ar[o][k] = 0ull; ai[o][k] = 0ull; }

#pragma unroll 2
    for (int c = 0; c < NC; c++) {
        ulonglong2 xrA = *(const ulonglong2*)&Xr_s[c][b0];
        ulonglong2 xrB = *(const ulonglong2*)&Xr_s[c][b0 + 4];
        ulonglong2 xiA = *(const ulonglong2*)&Xi_s[c][b0];
        ulonglong2 xiB = *(const ulonglong2*)&Xi_s[c][b0 + 4];
        float2 wrv = *(const float2*)&Wr[c][o0];
        float2 wiv = *(const float2*)&Wi[c][o0];
        unsigned long long xrp[4] = { xrA.x, xrA.y, xrB.x, xrB.y };
        unsigned long long xip[4] = { xiA.x, xiA.y, xiB.x, xiB.y };
#pragma unroll
        for (int o = 0; o < 2; o++) {
            float wrs = o ? wrv.y : wrv.x;
            float wis = o ? wiv.y : wiv.x;
            unsigned long long wrd = pk2(wrs, wrs);
            unsigned long long wid = pk2(wis, wis);
            unsigned long long wnd = pk2(-wis, -wis);
#pragma unroll
            for (int k = 0; k < 4; k++) {
                ffma2(ar[o][k], xrp[k], wrd);   // ar += xr*wr
                ffma2(ar[o][k], xip[k], wnd);   // ar -= xi*wi
                ffma2(ai[o][k], xrp[k], wid);   // ai += xr*wi
                ffma2(ai[o][k], xip[k], wrd);   // ai += xi*wr
            }
        }
    }
    float2* Yg = g_Yf + (size_t)f * (NB * NO);
#pragma unroll
    for (int k = 0; k < 4; k++) {
        float2 a0r = unpk2(ar[0][k]);
        float2 a0i = unpk2(ai[0][k]);
        float2 a1r = unpk2(ar[1][k]);
        float2 a1i = unpk2(ai[1][k]);
        *(float4*)&Yg[(b0 + 2 * k) * NO + o0]     = make_float4(a0r.x, a0i.x, a1r.x, a1i.x);
        *(float4*)&Yg[(b0 + 2 * k + 1) * NO + o0] = make_float4(a0r.y, a0i.y, a1r.y, a1i.y);
    }
}

// ---------------- K4: inverse column FFT (along h), to [bo][h][wp] (padded)
__global__ void __launch_bounds__(256) k4_colifft() {
    __shared__ float2 bufA[16 * LDF], bufB[16 * LDF];
    __shared__ float2 tw[64];
    init_tw(tw);
    int tid = threadIdx.x;
    int blk = blockIdx.x;
    int bt = blk / 17;
    int wt = blk % 17;
    int bo0 = bt << 2;
    int wp0 = wt << 2;
    for (int i = tid; i < 16 * NN; i += 256) {
        int bl = i & 3, wl = (i >> 2) & 3, h = i >> 4;
        int wp = wp0 + wl;
        int fi = (wl << 2) + bl;
        float2 v = make_float2(0.f, 0.f);
        if (wp < NH)
            v = g_Yf[((size_t)(wp * NN + h)) * NBO + bo0 + bl];
        bufA[fi * LDF + h] = v;
    }
    __syncthreads();
    fft128_block16<1>(bufA, bufB, tw);
    for (int i = tid; i < 16 * NN; i += 256) {
        int wl = i & 3, bl = (i >> 2) & 3, h = i >> 4;
        int wp = wp0 + wl;
        int fi = (wl << 2) + bl;
        if (wp < NH)
            g_Yc[((size_t)(bo0 + bl) * NN + h) * NHP + wp] = bufB[fi * LDF + h];
    }
}

// ---------------- K5: inverse row FFT with real-pair packing + bias + relu
__global__ void __launch_bounds__(256) k5_rowifft(const float* __restrict__ bias,
                                                  float* __restrict__ out) {
    __shared__ float2 bufA[16 * LDF], bufB[16 * LDF];
    __shared__ float2 tw[64];
    init_tw(tw);
    int tid = threadIdx.x;
    int blk = blockIdx.x;
    int bo = blk >> 2;
    int h0 = (blk & 3) << 5;              // 32 rows = 16 pairs
    int o  = bo & 63;
    const float2* Yrow = g_Yc + (size_t)bo * NN * NHP;
    for (int i = tid; i < 16 * NN; i += 256) {
        int p = i >> 7, w = i & 127;
        int wp = (w <= 64) ? w : (NN - w);
        float2 A0 = Yrow[(size_t)(h0 + 2 * p)     * NHP + wp];
        float2 A1 = Yrow[(size_t)(h0 + 2 * p + 1) * NHP + wp];
        if (w > 64) { A0.y = -A0.y; A1.y = -A1.y; }
        bufA[p * LDF + w] = make_float2(A0.x - A1.y, A0.y + A1.x);
    }
    __syncthreads();
    fft128_block16<1>(bufA, bufB, tw);
    float bv = bias[o];
    const float scale = 1.0f / 16384.0f;
    float* op = out + (size_t)bo * NN * NN;
    for (int i = tid; i < 16 * NN; i += 256) {
        int p = i >> 7, w = i & 127;
        float2 v = bufB[p * LDF + w];
        float v0 = v.x * scale + bv;
        float v1 = v.y * scale + bv;
        op[(size_t)(h0 + 2 * p)     * NN + w] = fmaxf(v0, 0.f);
        op[(size_t)(h0 + 2 * p + 1) * NN + w] = fmaxf(v1, 0.f);
    }
}

// ---------------- launch ----------------
extern "C" void kernel_launch(void* const* d_in, const int* in_sizes, int n_in,
                              void* d_out, int out_size) {
    const float* x    = (const float*)d_in[0];
    const float* wr   = (const float*)d_in[1];
    const float* wi   = (const float*)d_in[2];
    const float* bias = (const float*)d_in[3];
    float* out = (float*)d_out;

    k1_rowfft <<<NBC * 4, 256>>>(x);             // 8192 blocks
    kw_weff   <<<NC * NN * 5, 256>>>(wr, wi);    // 40960 blocks
    k2_colfft <<<NB * NH * 4, 256>>>();          // 8320 blocks
    k3_contract<<<NFREQ, 128>>>();               // 8320 blocks
    k4_colifft<<<(NBO / 4) * 17, 256>>>();       // 8704 blocks
    k5_rowifft<<<NBO * 4, 256>>>(bias, out);     // 8192 blocks
}

// round 7
// speedup vs baseline: 1.3867x; 1.0844x over previous
#include <cuda_runtime.h>
#include <cuda_fp16.h>

// Problem dims
#define NN    128            // H == W == kernel_size
#define NH    65             // half-spectrum width (N/2+1)
#define NHP   68             // padded row stride for Yc
#define NB    32             // batch
#define NC    64             // in channels
#define NO    64             // out channels
#define NBC   (NB*NC)        // 2048
#define NBO   (NB*NO)        // 2048
#define NFREQ (NH*NN)        // 8320, f = wp*128 + h
#define LDF   129            // smem FFT row stride
#define KWT   13             // kw tile width (5*13 = 65 = NH exactly)

// ---------------- scratch (device globals; allocation-free rule) ----------------
__device__ __half2 g_X1h[(size_t)NBC * NH * NN];    // [b*c][wp][h]   fp16 (r,i)
__device__ float2  g_Xf[(size_t)NFREQ * NB * NC];   // [f][b][c]
__device__ __half2 g_Wf[(size_t)NFREQ * NC * NO];   // [f][c][o]      fp16 (r,i)
__device__ __half2 g_Yfh[(size_t)NFREQ * NB * NO];  // [f][b][o]      fp16 (r,i)
__device__ float2  g_Yc[(size_t)NBO * NN * NHP];    // [bo][h][wp]

// ---------------- packed f32x2 helpers (FFMA2) ----------------
__device__ __forceinline__ unsigned long long pk2(float x, float y) {
    unsigned long long r;
    asm("mov.b64 %0, {%1, %2};" : "=l"(r) : "f"(x), "f"(y));
    return r;
}
__device__ __forceinline__ void ffma2(unsigned long long& d, unsigned long long a, unsigned long long b) {
    asm("fma.rn.f32x2 %0, %1, %2, %0;" : "+l"(d) : "l"(a), "l"(b));
}
__device__ __forceinline__ float2 unpk2(unsigned long long v) {
    float2 f;
    asm("mov.b64 {%0, %1}, %2;" : "=f"(f.x), "=f"(f.y) : "l"(v));
    return f;
}
__device__ __forceinline__ unsigned h2u(__half2 h) { return *(unsigned*)&h; }

// ---------------- FFT helpers ----------------
__device__ __forceinline__ void init_tw(float2* tw) {
    int tid = threadIdx.x;
    if (tid < 64) {
        float s, c;
        sincospif(-(float)tid * (1.0f / 64.0f), &s, &c);
        tw[tid] = make_float2(c, s);
    }
}

__device__ __forceinline__ float2 f2add(float2 a, float2 b) { return make_float2(a.x + b.x, a.y + b.y); }
__device__ __forceinline__ float2 f2sub(float2 a, float2 b) { return make_float2(a.x - b.x, a.y - b.y); }

template <int SIGN>
__device__ __forceinline__ float2 cmul_tw(float2 w, float2 z) {
    float wy = (SIGN < 0) ? w.y : -w.y;
    return make_float2(z.x * w.x - z.y * wy, z.x * wy + z.y * w.x);
}

#define SWZI(p) ((p) ^ ((((unsigned)(p)) >> 4) & 7))

// Fused 3x radix-2 (= radix-8) Stockham group. 16 threads per FFT.
template <int SIGN, int S, bool SWZ_ST, bool SWZ_LD>
__device__ __forceinline__ void radix8_group(const float2* src, float2* dst, const float2* tw) {
    int tid = threadIdx.x;
    int fi = tid >> 4;
    int i  = tid & 15;
    const int tk = i & ~(S - 1);
    const float2* Sr = src + fi * LDF;
    float2* Dr = dst + fi * LDF;

    float2 a[8];
#pragma unroll
    for (int k = 0; k < 8; k++) {
        int p = i + 16 * k;
        if (SWZ_LD) p = SWZI(p);
        a[k] = Sr[p];
    }
    float2 v[4], u[4];
#pragma unroll
    for (int k = 0; k < 4; k++) {
        v[k] = f2add(a[k], a[k + 4]);
        u[k] = cmul_tw<SIGN>(tw[tk + 16 * k], f2sub(a[k], a[k + 4]));
    }
    float2 w0 = tw[2 * tk], w1 = tw[2 * tk + 32];
    float2 g[4], h[4];
    g[0] = f2add(v[0], v[2]);  g[2] = cmul_tw<SIGN>(w0, f2sub(v[0], v[2]));
    g[1] = f2add(u[0], u[2]);  g[3] = cmul_tw<SIGN>(w0, f2sub(u[0], u[2]));
    h[0] = f2add(v[1], v[3]);  h[2] = cmul_tw<SIGN>(w1, f2sub(v[1], v[3]));
    h[1] = f2add(u[1], u[3]);  h[3] = cmul_tw<SIGN>(w1, f2sub(u[1], u[3]));
    float2 w2 = tw[4 * tk];
    float2 e[8];
#pragma unroll
    for (int k = 0; k < 4; k++) {
        e[k]     = f2add(g[k], h[k]);
        e[k + 4] = cmul_tw<SIGN>(w2, f2sub(g[k], h[k]));
    }
    const int Q = i + 7 * tk;
#pragma unroll
    for (int k = 0; k < 8; k++) {
        int p = Q + k * S;
        if (SWZ_ST) p = SWZI(p);
        Dr[p] = e[k];
    }
}

// 16 FFTs of length 128 per 256-thread block. Input bufA, result bufB.
template <int SIGN>
__device__ __forceinline__ void fft128_block16(float2* bufA, float2* bufB, const float2* tw) {
    radix8_group<SIGN, 1, true,  false>(bufA, bufB, tw);
    __syncthreads();
    radix8_group<SIGN, 8, false, true >(bufB, bufA, tw);
    __syncthreads();
    int tid = threadIdx.x;
#pragma unroll
    for (int itb = 0; itb < 4; itb++) {
        int it  = tid + itb * 256;
        int f2  = it >> 6;
        int idx = it & 63;
        float2 x = bufA[f2 * LDF + idx];
        float2 y = bufA[f2 * LDF + idx + 64];
        bufB[f2 * LDF + idx]      = f2add(x, y);
        bufB[f2 * LDF + idx + 64] = f2sub(x, y);
    }
    __syncthreads();
}

// ---------------- K1: forward row FFT with real-pair packing, fp16 output.
__global__ void __launch_bounds__(256) k1_rowfft(const float* __restrict__ x) {
    __shared__ float2 bufA[16 * LDF], bufB[16 * LDF];
    __shared__ float2 tw[64];
    init_tw(tw);
    int tid = threadIdx.x;
    int blk = blockIdx.x;
    int bc = blk >> 2;
    int h0 = (blk & 3) << 5;              // 32 rows
    const float* xp = x + (size_t)bc * NN * NN + (size_t)h0 * NN;
    for (int i = tid; i < 16 * NN; i += 256) {
        int p = i >> 7, w = i & 127;
        bufA[p * LDF + w] = make_float2(xp[(2 * p) * NN + w], xp[(2 * p + 1) * NN + w]);
    }
    __syncthreads();
    fft128_block16<-1>(bufA, bufB, tw);
    __half2* out = g_X1h + (size_t)bc * NH * NN;
    for (int i = tid; i < NH * 16; i += 256) {
        int p = i & 15, wp = i >> 4;
        float2 A = bufB[p * LDF + wp];
        float2 B = bufB[p * LDF + ((NN - wp) & 127)];
        __half2 X0 = __floats2half2_rn(0.5f * (A.x + B.x), 0.5f * (A.y - B.y));
        __half2 X1 = __floats2half2_rn(0.5f * (A.y + B.y), 0.5f * (B.x - A.x));
        *(uint2*)&out[(size_t)wp * NN + h0 + 2 * p] = make_uint2(h2u(X0), h2u(X1));
    }
}

// ---------------- K2: forward column FFT, scatter to freq-major [f][b][c]
__global__ void __launch_bounds__(256) k2_colfft() {
    __shared__ float2 bufA[16 * LDF], bufB[16 * LDF];
    __shared__ float2 tw[64];
    init_tw(tw);
    int tid = threadIdx.x;
    int blk = blockIdx.x;
    int b   = blk / (NH * 4);
    int rem = blk % (NH * 4);
    int wp  = rem >> 2;
    int c0  = (rem & 3) << 4;
    for (int i = tid; i < 16 * NN; i += 256) {
        int h = i & 127, cl = i >> 7;
        bufA[cl * LDF + h] = __half22float2(
            g_X1h[((size_t)(b * NC + c0 + cl) * NH + wp) * NN + h]);
    }
    __syncthreads();
    fft128_block16<-1>(bufA, bufB, tw);
    for (int i = tid; i < 16 * NN; i += 256) {
        int cl = i & 15, h = i >> 4;
        g_Xf[((size_t)(wp * NN + h)) * NBC + b * NC + c0 + cl] = bufB[cl * LDF + h];
    }
}

// ---------------- KW: Weff[f][c][o] = 0.5*(W[k] + conj(W[-k])), fp16 output.
__global__ void __launch_bounds__(256) kw_weff(const float* __restrict__ wr,
                                               const float* __restrict__ wi) {
    __shared__ __half2 S[64][KWT + 3];
    int tid = threadIdx.x;
    int blk = blockIdx.x;                 // c*(128*5) + h*5 + wt
    int c   = blk / (NN * 5);
    int rem = blk % (NN * 5);
    int h   = rem / 5;
    int wt  = rem % 5;
    int wp0 = wt * KWT;
    int h2  = (NN - h) & 127;
    for (int i = tid; i < 64 * 16; i += 256) {
        int wl = i & 15, o = i >> 4;
        if (wl < KWT) {
            int wp = wp0 + wl;            // < 65
            int w2 = (NN - wp) & 127;
            size_t base = (size_t)(o * NC + c) * (NN * NN);
            float a1 = wr[base + (size_t)h  * NN + wp];
            float b1 = wi[base + (size_t)h  * NN + wp];
            float a2 = wr[base + (size_t)h2 * NN + w2];
            float b2 = wi[base + (size_t)h2 * NN + w2];
            S[o][wl] = __floats2half2_rn(0.5f * (a1 + a2), 0.5f * (b1 - b2));
        }
    }
    __syncthreads();
    for (int i = tid; i < 64 * 16; i += 256) {
        int o = i & 63, wl = i >> 6;
        if (wl < KWT) {
            int wp = wp0 + wl;
            g_Wf[((size_t)(wp * NN + h)) * (NC * NO) + c * NO + o] = S[o][wl];
        }
    }
}

// ---------------- K3: per-frequency complex GEMM  Y[b][o] = sum_c X[b][c] * Weff[c][o]
// 128 threads; 2 outputs x 8 batches per thread. W kept fp16 in smem
// (35KB total -> 6 blocks/SM). X loads as ulonglong2 (no repack MOVs).
__global__ void __launch_bounds__(128, 6) k3_contract() {
    __shared__ __align__(16) float  Xr_s[NC][NB + 4];   // 9.2 KB
    __shared__ __align__(16) float  Xi_s[NC][NB + 4];   // 9.2 KB
    __shared__ __align__(8)  __half2 Wr2[NC][NO / 2];   // 8 KB (o-pairs, real)
    __shared__ __align__(8)  __half2 Wi2[NC][NO / 2];   // 8 KB (o-pairs, imag)
    int tid = threadIdx.x;
    int f = blockIdx.x;
    const float2* __restrict__ Xg = g_Xf + (size_t)f * (NB * NC);
    const uint4* __restrict__ Wg4 = (const uint4*)(g_Wf + (size_t)f * (NC * NO));
    for (int i = tid; i < NB * NC; i += 128) {
        float2 v = Xg[i];
        int b = i >> 6, c = i & 63;
        Xr_s[c][b] = v.x;
        Xi_s[c][b] = v.y;
    }
    for (int i = tid; i < (NC * NO) / 4; i += 128) {   // uint4 = 4 half2 = 4 o's
        uint4 v = Wg4[i];
        int base = i * 4;
        int c = base >> 6, o = base & 63;
        __half2 p0 = *(__half2*)&v.x, p1 = *(__half2*)&v.y;
        __half2 p2 = *(__half2*)&v.z, p3 = *(__half2*)&v.w;
        __half2 r01 = __lows2half2(p0, p1), i01 = __highs2half2(p0, p1);
        __half2 r23 = __lows2half2(p2, p3), i23 = __highs2half2(p2, p3);
        *(uint2*)&Wr2[c][o >> 1] = make_uint2(h2u(r01), h2u(r23));
        *(uint2*)&Wi2[c][o >> 1] = make_uint2(h2u(i01), h2u(i23));
    }
    __syncthreads();

    int b0 = (tid & 3) << 3;              // 8 batches per thread
    int op = tid >> 2;                    // o-pair index; o0 = 2*op
    unsigned long long ar[2][4], ai[2][4];
#pragma unroll
    for (int o = 0; o < 2; o++)
#pragma unroll
        for (int k = 0; k < 4; k++) { ar[o][k] = 0ull; ai[o][k] = 0ull; }

#pragma unroll 2
    for (int c = 0; c < NC; c++) {
        ulonglong2 xrA = *(const ulonglong2*)&Xr_s[c][b0];
        ulonglong2 xrB = *(const ulonglong2*)&Xr_s[c][b0 + 4];
        ulonglong2 xiA = *(const ulonglong2*)&Xi_s[c][b0];
        ulonglong2 xiB = *(const ulonglong2*)&Xi_s[c][b0 + 4];
        float2 wrv = __half22float2(Wr2[c][op]);
        float2 wiv = __half22float2(Wi2[c][op]);
        unsigned long long xrp[4] = { xrA.x, xrA.y, xrB.x, xrB.y };
        unsigned long long xip[4] = { xiA.x, xiA.y, xiB.x, xiB.y };
#pragma unroll
        for (int o = 0; o < 2; o++) {
            float wrs = o ? wrv.y : wrv.x;
            float wis = o ? wiv.y : wiv.x;
            unsigned long long wrd = pk2(wrs, wrs);
            unsigned long long wid = pk2(wis, wis);
            unsigned long long wnd = pk2(-wis, -wis);
#pragma unroll
            for (int k = 0; k < 4; k++) {
                ffma2(ar[o][k], xrp[k], wrd);   // ar += xr*wr
                ffma2(ar[o][k], xip[k], wnd);   // ar -= xi*wi
                ffma2(ai[o][k], xrp[k], wid);   // ai += xr*wi
                ffma2(ai[o][k], xip[k], wrd);   // ai += xi*wr
            }
        }
    }
    __half2* Ygh = g_Yfh + (size_t)f * (NB * NO);
    int o0 = op << 1;
#pragma unroll
    for (int k = 0; k < 4; k++) {
        float2 a0r = unpk2(ar[0][k]);
        float2 a0i = unpk2(ai[0][k]);
        float2 a1r = unpk2(ar[1][k]);
        float2 a1i = unpk2(ai[1][k]);
        __half2 e00 = __floats2half2_rn(a0r.x, a0i.x);   // (b0+2k,   o0)
        __half2 e01 = __floats2half2_rn(a1r.x, a1i.x);   // (b0+2k,   o0+1)
        __half2 e10 = __floats2half2_rn(a0r.y, a0i.y);   // (b0+2k+1, o0)
        __half2 e11 = __floats2half2_rn(a1r.y, a1i.y);   // (b0+2k+1, o0+1)
        *(uint2*)&Ygh[(b0 + 2 * k) * NO + o0]     = make_uint2(h2u(e00), h2u(e01));
        *(uint2*)&Ygh[(b0 + 2 * k + 1) * NO + o0] = make_uint2(h2u(e10), h2u(e11));
    }
}

// ---------------- K4: inverse column FFT (along h), to [bo][h][wp] (padded)
__global__ void __launch_bounds__(256) k4_colifft() {
    __shared__ float2 bufA[16 * LDF], bufB[16 * LDF];
    __shared__ float2 tw[64];
    init_tw(tw);
    int tid = threadIdx.x;
    int blk = blockIdx.x;
    int bt = blk / 17;
    int wt = blk % 17;
    int bo0 = bt << 2;
    int wp0 = wt << 2;
    for (int i = tid; i < 4 * NN; i += 256) {          // 512 uint4 loads (4 bo each)
        int wl = i & 3, h = i >> 2;
        int wp = wp0 + wl;
        uint4 v = make_uint4(0u, 0u, 0u, 0u);
        if (wp < NH)
            v = *(const uint4*)&g_Yfh[((size_t)(wp * NN + h)) * NBO + bo0];
        const unsigned* vp = &v.x;
#pragma unroll
        for (int bl = 0; bl < 4; bl++) {
            __half2 hv = *(__half2*)&vp[bl];
            bufA[((wl << 2) + bl) * LDF + h] = __half22float2(hv);
        }
    }
    __syncthreads();
    fft128_block16<1>(bufA, bufB, tw);
    for (int i = tid; i < 16 * NN; i += 256) {
        int wl = i & 3, bl = (i >> 2) & 3, h = i >> 4;
        int wp = wp0 + wl;
        int fi = (wl << 2) + bl;
        if (wp < NH)
            g_Yc[((size_t)(bo0 + bl) * NN + h) * NHP + wp] = bufB[fi * LDF + h];
    }
}

// ---------------- K5: inverse row FFT with real-pair packing + bias + relu
__global__ void __launch_bounds__(256) k5_rowifft(const float* __restrict__ bias,
                                                  float* __restrict__ out) {
    __shared__ float2 bufA[16 * LDF], bufB[16 * LDF];
    __shared__ float2 tw[64];
    init_tw(tw);
    int tid = threadIdx.x;
    int blk = blockIdx.x;
    int bo = blk >> 2;
    int h0 = (blk & 3) << 5;              // 32 rows = 16 pairs
    int o  = bo & 63;
    const float2* Yrow = g_Yc + (size_t)bo * NN * NHP;
    for (int i = tid; i < 16 * NN; i += 256) {
        int p = i >> 7, w = i & 127;
        int wp = (w <= 64) ? w : (NN - w);
        float2 A0 = Yrow[(size_t)(h0 + 2 * p)     * NHP + wp];
        float2 A1 = Yrow[(size_t)(h0 + 2 * p + 1) * NHP + wp];
        if (w > 64) { A0.y = -A0.y; A1.y = -A1.y; }
        bufA[p * LDF + w] = make_float2(A0.x - A1.y, A0.y + A1.x);
    }
    __syncthreads();
    fft128_block16<1>(bufA, bufB, tw);
    float bv = bias[o];
    const float scale = 1.0f / 16384.0f;
    float* op = out + (size_t)bo * NN * NN;
    for (int i = tid; i < 16 * NN; i += 256) {
        int p = i >> 7, w = i & 127;
        float2 v = bufB[p * LDF + w];
        float v0 = v.x * scale + bv;
        float v1 = v.y * scale + bv;
        op[(size_t)(h0 + 2 * p)     * NN + w] = fmaxf(v0, 0.f);
        op[(size_t)(h0 + 2 * p + 1) * NN + w] = fmaxf(v1, 0.f);
    }
}

// ---------------- launch ----------------
extern "C" void kernel_launch(void* const* d_in, const int* in_sizes, int n_in,
                              void* d_out, int out_size) {
    const float* x    = (const float*)d_in[0];
    const float* wr   = (const float*)d_in[1];
    const float* wi   = (const float*)d_in[2];
    const float* bias = (const float*)d_in[3];
    float* out = (float*)d_out;

    k1_rowfft <<<NBC * 4, 256>>>(x);             // 8192 blocks
    kw_weff   <<<NC * NN * 5, 256>>>(wr, wi);    // 40960 blocks
    k2_colfft <<<NB * NH * 4, 256>>>();          // 8320 blocks
    k3_contract<<<NFREQ, 128>>>();               // 8320 blocks
    k4_colifft<<<(NBO / 4) * 17, 256>>>();       // 8704 blocks
    k5_rowifft<<<NBO * 4, 256>>>(bias, out);     // 8192 blocks
}